// round 8
// baseline (speedup 1.0000x reference)
#include <cuda_runtime.h>
#include <cuda_fp16.h>

#define IMG 4096
#define OW  4097
#define SW  29          // output columns per warp strip
#define RPB 32          // output rows per block
#define CC 0.92387953251128674f
#define SS 0.38268343236508978f

__device__ __forceinline__ unsigned int hadd2u(unsigned int a, unsigned int b) {
    __half2 ha = *reinterpret_cast<__half2*>(&a);
    __half2 hb = *reinterpret_cast<__half2*>(&b);
    __half2 hr = __hadd2(ha, hb);
    return *reinterpret_cast<unsigned int*>(&hr);
}
__device__ __forceinline__ float2 h2f2u(unsigned int a) {
    __half2 h = *reinterpret_cast<__half2*>(&a);
    return __half22float2(h);
}

// Load input row RY, produce rolling column stats for this lane's hist column:
//   S = c0 + 2*c1 + c2,  D = c2 - c0   (c* = input at xh-1, xh, xh+1)
#define LOAD_ROW(RY, S, D) do {                                               \
    int  _ry  = (RY);                                                         \
    bool _rok = (_ry >= 0) && (_ry < IMG);                                    \
    const float* _rp = x + (size_t)_ry * IMG;                                 \
    float _v = (_rok && xi_ok) ? __ldg(_rp + xi) : 0.0f;                      \
    float _e = (_rok && xe_ok) ? __ldg(_rp + xe) : 0.0f;                      \
    float _e0 = __shfl_sync(0xffffffffu, _e, 0);                              \
    float _e1 = __shfl_sync(0xffffffffu, _e, 1);                              \
    float _c1 = __shfl_down_sync(0xffffffffu, _v, 1);                         \
    float _c2 = __shfl_down_sync(0xffffffffu, _v, 2);                         \
    if (lane == 31) _c1 = _e0;                                                \
    if (lane == 30) _c2 = _e0;                                                \
    if (lane == 31) _c2 = _e1;                                                \
    (S) = fmaf(2.0f, _c1, _v) + _c2;                                          \
    (D) = _c2 - _v;                                                           \
} while (0)

#define TAP(MS, PH) {                                                         \
    if ((PH) == 0u) a0 = hadd2u(a0, (MS));                                    \
    if ((PH) == 1u) a1 = hadd2u(a1, (MS));                                    \
    if ((PH) == 2u) a2 = hadd2u(a2, (MS));                                    \
    if ((PH) == 3u) a3 = hadd2u(a3, (MS));                                    \
}

// One hist row YH: sobel -> bin -> packed one-hot -> horizontal 4-tap via
// shuffles -> vertical running-window update -> emit output row YH-1.
#define STEP(K, YH) do {                                                      \
    LOAD_ROW((YH) + 1, s2, d2);                                               \
    float dx = fmaf(2.0f, d1, d0) + d2;                                       \
    float dy = s2 - s0;                                                       \
    float cdx = CC * dx, sdx = SS * dx;                                       \
    float cdy = CC * dy, sdy = SS * dy;                                       \
    float p = cdx + sdy, q = sdx + cdy;                                       \
    float r = cdy - sdx, t = sdy - cdx;                                       \
    float bv = p; int bi = 0;                                                 \
    if ( q > bv) { bv =  q; bi = 1; }                                         \
    if ( r > bv) { bv =  r; bi = 2; }                                         \
    if ( t > bv) { bv =  t; bi = 3; }                                         \
    if (-p > bv) { bv = -p; bi = 4; }                                         \
    if (-q > bv) { bv = -q; bi = 5; }                                         \
    if (-r > bv) { bv = -r; bi = 6; }                                         \
    if (-t > bv) { bv = -t; bi = 7; }                                         \
    float m2v = fmaf(dx, dx, dy * dy);                                        \
    float mag = (m2v > 0.0f) ? m2v * rsqrtf(m2v) : 0.0f;                      \
    if (!(xh_ok && (YH) >= 0 && (YH) < IMG)) mag = 0.0f;                      \
    unsigned int msh =                                                        \
        (unsigned int)__half_as_ushort(__float2half_rn(mag)) << ((bi & 1) << 4); \
    unsigned int ph = (unsigned int)(bi >> 1);                                \
    unsigned int m1s = __shfl_down_sync(0xffffffffu, msh, 1);                 \
    unsigned int p1s = __shfl_down_sync(0xffffffffu, ph , 1);                 \
    unsigned int m2s = __shfl_down_sync(0xffffffffu, msh, 2);                 \
    unsigned int p2s = __shfl_down_sync(0xffffffffu, ph , 2);                 \
    unsigned int m3s = __shfl_down_sync(0xffffffffu, msh, 3);                 \
    unsigned int p3s = __shfl_down_sync(0xffffffffu, ph , 3);                 \
    unsigned int a0 = 0u, a1 = 0u, a2 = 0u, a3 = 0u;                          \
    TAP(msh, ph); TAP(m1s, p1s); TAP(m2s, p2s); TAP(m3s, p3s);                \
    { float2 f;                                                               \
      f = h2f2u(a0); w0.x += f.x; w0.y += f.y;                                \
      f = h2f2u(a1); w1.x += f.x; w1.y += f.y;                                \
      f = h2f2u(a2); w2.x += f.x; w2.y += f.y;                                \
      f = h2f2u(a3); w3.x += f.x; w3.y += f.y; }                              \
    int yo = (YH) - 1;                                                        \
    if (emit_x && yo >= Y0 && yo < yend) {                                    \
        size_t b = (size_t)yo * OW + gx;                                      \
        out[b]          = w0.x; out[PL + b]     = w0.y;                       \
        out[2 * PL + b] = w1.x; out[3 * PL + b] = w1.y;                       \
        out[4 * PL + b] = w2.x; out[5 * PL + b] = w2.y;                       \
        out[6 * PL + b] = w3.x; out[7 * PL + b] = w3.y;                       \
    }                                                                         \
    { float2 f;                                                               \
      f = h2f2u(ring[((K) + 1) & 3][0]); w0.x -= f.x; w0.y -= f.y;            \
      f = h2f2u(ring[((K) + 1) & 3][1]); w1.x -= f.x; w1.y -= f.y;            \
      f = h2f2u(ring[((K) + 1) & 3][2]); w2.x -= f.x; w2.y -= f.y;            \
      f = h2f2u(ring[((K) + 1) & 3][3]); w3.x -= f.x; w3.y -= f.y; }          \
    ring[(K)][0] = a0; ring[(K)][1] = a1;                                     \
    ring[(K)][2] = a2; ring[(K)][3] = a3;                                     \
    s0 = s1; s1 = s2; d0 = d1; d1 = d2;                                       \
} while (0)

__global__ __launch_bounds__(256, 4)
void sift_march_kernel(const float* __restrict__ x, float* __restrict__ out)
{
    const int lane = threadIdx.x & 31;
    const int wid  = threadIdx.x >> 5;
    const int x0   = (blockIdx.x * 8 + wid) * SW;  // strip origin (output x)
    const int Y0   = blockIdx.y * RPB;
    const int yend = (Y0 + RPB < OW) ? (Y0 + RPB) : OW;

    const int  xi     = x0 - 3 + lane;             // input col (main load)
    const bool xi_ok  = (xi >= 0) && (xi < IMG);
    const int  xe     = x0 + 29 + lane;            // extra input cols (lanes 0,1)
    const bool xe_ok  = (lane < 2) && (xe < IMG);
    const int  xh     = x0 - 2 + lane;             // this lane's hist col
    const bool xh_ok  = (xh >= 0) && (xh < IMG);
    const int  gx     = x0 + lane;                 // this lane's output col
    const bool emit_x = (lane < SW) && (gx < OW);
    const size_t PL   = (size_t)OW * OW;

    // vertical window state
    unsigned int ring[4][4];
    #pragma unroll
    for (int i = 0; i < 4; ++i) {
        #pragma unroll
        for (int j = 0; j < 4; ++j) ring[i][j] = 0u;
    }
    float2 w0 = make_float2(0.f, 0.f), w1 = make_float2(0.f, 0.f);
    float2 w2 = make_float2(0.f, 0.f), w3 = make_float2(0.f, 0.f);

    float s0, s1, s2, d0, d1, d2;
    LOAD_ROW(Y0 - 3, s0, d0);
    LOAD_ROW(Y0 - 2, s1, d1);

    #pragma unroll 1
    for (int t = 0; t < 9; ++t) {
        int yb = Y0 - 2 + 4 * t;
        STEP(0, yb);
        STEP(1, yb + 1);
        STEP(2, yb + 2);
        STEP(3, yb + 3);
    }
}

extern "C" void kernel_launch(void* const* d_in, const int* in_sizes, int n_in,
                              void* d_out, int out_size)
{
    const float* x   = (const float*)d_in[0];
    float*       out = (float*)d_out;
    // 142 strips of 29 cols -> 18 blocks of 8 warps; 129 row chunks of 32
    dim3 grid(18, 129);
    sift_march_kernel<<<grid, 256>>>(x, out);
}

// round 9
// speedup vs baseline: 1.5392x; 1.5392x over previous
#include <cuda_runtime.h>
#include <cuda_fp16.h>

#define IMG_H 4096
#define IMG_W 4096
#define OUT_H 4097
#define OUT_W 4097
#define TILE  32
#define HIST  35   // TILE + 3
#define INW   37   // HIST + 2 (sobel halo)
#define INP   38   // padded input row stride (words)
#define HP    37   // packed (bi<<16|fp16 mag) row stride
#define RSU   36   // s_rs row stride in uint4

// cos(pi/8), sin(pi/8)
#define CC 0.92387953251128674f
#define SS 0.38268343236508978f

__device__ __forceinline__ unsigned int hadd2u(unsigned int a, unsigned int b) {
    __half2 ha = *reinterpret_cast<__half2*>(&a);
    __half2 hb = *reinterpret_cast<__half2*>(&b);
    __half2 hr = __hadd2(ha, hb);
    return *reinterpret_cast<unsigned int*>(&hr);
}
__device__ __forceinline__ float2 h2f2u(unsigned int a) {
    __half2 h = *reinterpret_cast<__half2*>(&a);
    return __half22float2(h);
}

__global__ __launch_bounds__(256, 6)
void sift_fused_kernel(const float* __restrict__ x, float* __restrict__ out)
{
    // rs: [hist row][x] of 8 x fp16 channel row-sums; lane(x) contiguous uint4.
    __shared__ uint4        s_rs[HIST][RSU];   // 20160 B (aliased as input tile)
    __shared__ unsigned int s_pk[HIST][HP];    //  5180 B
    // total 25340 B -> 6+ CTAs/SM (reg-capped at 6)

    float* s_in = (float*)s_rs;   // [INW][INP] = 5624 B, dead after stage 2

    const int X0   = blockIdx.x * TILE;
    const int Y0   = blockIdx.y * TILE;
    const int tid  = threadIdx.x;
    const int lane = tid & 31;
    const int wrow = tid >> 5;    // 0..7

    const bool interior =
        blockIdx.x >= 1 && blockIdx.x <= 126 &&
        blockIdx.y >= 1 && blockIdx.y <= 126;

    // ---- Stage 1: load input tile (origin Y0-3, X0-3) ----
    if (interior) {
        const float* src = x + (size_t)(Y0 - 3) * IMG_W + (X0 - 3);
        #pragma unroll
        for (int it = 0; it < 5; ++it) {
            int r = wrow + 8 * it;
            if (r < INW) {
                const float* row = src + (size_t)r * IMG_W;
                s_in[r * INP + lane] = row[lane];
                if (lane < INW - 32)
                    s_in[r * INP + 32 + lane] = row[32 + lane];
            }
        }
    } else {
        #pragma unroll
        for (int it = 0; it < 5; ++it) {
            int r = wrow + 8 * it;
            if (r < INW) {
                int  gy    = Y0 - 3 + r;
                bool rowok = (gy >= 0) && (gy < IMG_H);
                int  gx    = X0 - 3 + lane;
                float v = 0.0f;
                if (rowok && gx >= 0 && gx < IMG_W)
                    v = x[(size_t)gy * IMG_W + gx];
                s_in[r * INP + lane] = v;
                if (lane < INW - 32) {
                    int gx2 = gx + 32;
                    float v2 = 0.0f;
                    if (rowok && gx2 >= 0 && gx2 < IMG_W)
                        v2 = x[(size_t)gy * IMG_W + gx2];
                    s_in[r * INP + 32 + lane] = v2;
                }
            }
        }
    }
    __syncthreads();

    // ---- Stage 2: column-sliding Sobel + argmax bin + packed store ----
    // 35 columns x 7 strips of 5 rows = 245 segments; rolling row stats.
    if (tid < 245) {
        int col   = tid % 35;
        int strip = tid / 35;
        int h0    = strip * 5;
        const float* base = s_in + h0 * INP + col;

        float c0 = base[0],       c1 = base[1],       c2 = base[2];
        float d0 = c2 - c0;
        float s0 = fmaf(2.0f, c1, c0) + c2;
        c0 = base[INP]; c1 = base[INP + 1]; c2 = base[INP + 2];
        float d1 = c2 - c0;
        float s1 = fmaf(2.0f, c1, c0) + c2;

        const int  gx    = X0 - 2 + col;
        const bool colok = (gx >= 0) && (gx < IMG_W);

        #pragma unroll
        for (int r = 0; r < 5; ++r) {
            const float* rb = base + (r + 2) * INP;
            c0 = rb[0]; c1 = rb[1]; c2 = rb[2];
            float d2 = c2 - c0;
            float s2 = fmaf(2.0f, c1, c0) + c2;

            float dx = fmaf(2.0f, d1, d0) + d2;
            float dy = s2 - s0;

            float cdx = CC * dx, sdx = SS * dx;
            float cdy = CC * dy, sdy = SS * dy;
            float p  = cdx + sdy;
            float q  = sdx + cdy;
            float r2 = cdy - sdx;
            float t2 = sdy - cdx;

            float bv = p; int bi = 0;
            if ( q  > bv) { bv =  q;  bi = 1; }
            if ( r2 > bv) { bv =  r2; bi = 2; }
            if ( t2 > bv) { bv =  t2; bi = 3; }
            if (-p  > bv) { bv = -p;  bi = 4; }
            if (-q  > bv) { bv = -q;  bi = 5; }
            if (-r2 > bv) { bv = -r2; bi = 6; }
            if (-t2 > bv) { bv = -t2; bi = 7; }

            float mag = sqrtf(fmaf(dx, dx, dy * dy));
            unsigned int magh =
                (unsigned int)__half_as_ushort(__float2half_rn(mag));
            unsigned int bits = ((unsigned int)bi << 16) | magh;

            if (!interior) {
                int gy = Y0 - 2 + h0 + r;
                if (!(colok && gy >= 0 && gy < IMG_H)) bits = 0u;
            }
            s_pk[h0 + r][col] = bits;

            d0 = d1; d1 = d2;
            s0 = s1; s1 = s2;
        }
    }
    __syncthreads();

    // ---- Stage 3: horizontal 4-tap row sums, shift-scatter into fp16 ----
    // rs[h][x].{a0..a3} = half2 pairs (ch0,ch1)..(ch6,ch7)
    #pragma unroll
    for (int it = 0; it < 5; ++it) {
        int e = tid + 256 * it;
        if (e < HIST * TILE) {
            int h  = e >> 5;
            int ox = e & 31;
            unsigned int a0 = 0u, a1 = 0u, a2 = 0u, a3 = 0u;
            #pragma unroll
            for (int k = 0; k < 4; k++) {
                unsigned int u  = s_pk[h][ox + k];
                unsigned int sh = (u & 0xFFFFu) << ((u >> 12) & 0x10u);
                unsigned int w  = u >> 17;
                if (w == 0u) a0 = hadd2u(a0, sh);
                if (w == 1u) a1 = hadd2u(a1, sh);
                if (w == 2u) a2 = hadd2u(a2, sh);
                if (w == 3u) a3 = hadd2u(a3, sh);
            }
            s_rs[h][ox] = make_uint4(a0, a1, a2, a3);
        }
    }
    __syncthreads();

    // ---- Stage 4: vertical 4-tap sliding sum (fp32) + store 8 channels ----
    const int    gx    = X0 + lane;
    const size_t plane = (size_t)OUT_H * OUT_W;
    const int    oy0   = wrow * 4;          // 4 consecutive rows per thread

    float b0 = 0.f, b1 = 0.f, b2 = 0.f, b3 = 0.f;
    float b4 = 0.f, b5 = 0.f, b6 = 0.f, b7 = 0.f;

    #define ROW_ACC(V, SGN) do {                                          \
        uint4 _v = (V);                                                   \
        float2 _f0 = h2f2u(_v.x); float2 _f1 = h2f2u(_v.y);               \
        float2 _f2 = h2f2u(_v.z); float2 _f3 = h2f2u(_v.w);               \
        b0 SGN _f0.x; b1 SGN _f0.y; b2 SGN _f1.x; b3 SGN _f1.y;           \
        b4 SGN _f2.x; b5 SGN _f2.y; b6 SGN _f3.x; b7 SGN _f3.y;           \
    } while (0)

    ROW_ACC(s_rs[oy0][lane], +=);
    ROW_ACC(s_rs[oy0 + 1][lane], +=);
    ROW_ACC(s_rs[oy0 + 2][lane], +=);
    ROW_ACC(s_rs[oy0 + 3][lane], +=);

    #pragma unroll
    for (int r = 0; r < 4; r++) {
        if (r > 0) {
            ROW_ACC(s_rs[oy0 + r + 3][lane], +=);
            ROW_ACC(s_rs[oy0 + r - 1][lane], -=);
        }
        int gy = Y0 + oy0 + r;
        if (gy < OUT_H && gx < OUT_W) {
            size_t base = (size_t)gy * OUT_W + gx;
            out[base]              = b0;
            out[plane + base]      = b1;
            out[2 * plane + base]  = b2;
            out[3 * plane + base]  = b3;
            out[4 * plane + base]  = b4;
            out[5 * plane + base]  = b5;
            out[6 * plane + base]  = b6;
            out[7 * plane + base]  = b7;
        }
    }
    #undef ROW_ACC
}

extern "C" void kernel_launch(void* const* d_in, const int* in_sizes, int n_in,
                              void* d_out, int out_size)
{
    const float* x   = (const float*)d_in[0];
    float*       out = (float*)d_out;
    dim3 grid((OUT_W + TILE - 1) / TILE, (OUT_H + TILE - 1) / TILE);  // 129 x 129
    sift_fused_kernel<<<grid, 256>>>(x, out);
}